// round 1
// baseline (speedup 1.0000x reference)
#include <cuda_runtime.h>

// ---------------------------------------------------------------------------
// weighted_loss: scalar loss over B=4.2M rows, 3 tasks (head/chest/neck).
// Issue-bound design: branchless selects, poly-exp (no MUFU), LUT for 1.1^n.
// ---------------------------------------------------------------------------

__device__ double g_sum;

__global__ void zero_kernel() { g_sum = 0.0; }

__device__ __forceinline__ float stepf(float x, float t) {
    return (x >= t) ? 1.0f : 0.0f;
}

// exp(u) for u in [-0.23, 0], degree-5 Horner. abs err < 2e-7.
__device__ __forceinline__ float exp_small(float u) {
    float h = fmaf(u, 8.3333333e-3f, 4.1666668e-2f);  // 1/120, 1/24
    h = fmaf(u, h, 0.16666667f);                       // 1/6
    h = fmaf(u, h, 0.5f);
    h = fmaf(u, h, 1.0f);
    return fmaf(u, h, 1.0f);
}

// |ais(p) - ais(t)| for 5 sorted thresholds, as a small nonneg float
__device__ __forceinline__ float aisdiff5(float p, float t,
                                          float t0, float t1, float t2,
                                          float t3, float t4) {
    float d = stepf(p, t0) - stepf(t, t0);
    d += stepf(p, t1) - stepf(t, t1);
    d += stepf(p, t2) - stepf(t, t2);
    d += stepf(p, t3) - stepf(t, t3);
    d += stepf(p, t4) - stepf(t, t4);
    return fabsf(d);
}

// Returns w_mid = 1 + piecewise_linear(yt, yp) with mid = 1.
//   [0,a): 1 + yt/a        [a,b]: 2        (b,c): 2 - (yt-b)/(c-b)
//   [c,d]: 1               (d,inf): exp(-ln2*(yt-d)/d)
//   + 1 extra if yp < 0.
// C3 = 2 + b*inv_cb ; neg_k = -ln2/d ; note k*d = ln2 so u = ln2 + neg_k*yt.
__device__ __forceinline__ float wmid_f(float yt, float yp,
                                        float a, float b, float c, float d,
                                        float inv_a, float neg_inv_cb,
                                        float C3, float neg_k) {
    float w1m = fmaf(yt, inv_a, 1.0f);        // region [0,a)
    float w3m = fmaf(yt, neg_inv_cb, C3);     // region (b,c)
    float u   = fmaf(neg_k, yt, 0.69314718f); // = -k*(yt-d)
    float e   = exp_small(u);                 // region (d,inf): exp(u)
    float lo  = (yt < a)  ? w1m : 2.0f;       // covers [0,b]
    float hi  = (yt <= d) ? 1.0f : e;         // covers [c,inf)
    hi        = (yt < c)  ? w3m : hi;         // covers (b,inf)
    float w   = (yt <= b) ? lo : hi;
    w += (yp < 0.0f) ? 1.0f : 0.0f;
    return w;
}

__device__ __forceinline__ float row_loss(const float* __restrict__ sW,
                                          float ph, float pd, float pn,
                                          float th, float td, float tn,
                                          int o) {
    // ---- head: thr {150,500,1000,1800,2600}; a=80 b=1500 c=1750 d=2000
    float dh = aisdiff5(ph, th, 150.0f, 500.0f, 1000.0f, 1800.0f, 2600.0f);
    float mh = wmid_f(th, ph, 80.0f, 1500.0f, 1750.0f, 2000.0f,
                      0.0125f, -0.004f, 8.0f, -3.4657359e-4f);
    float L = fabsf(ph - th) * sW[(int)dh] * mh;

    // ---- chest: thr {22,35,45,55,65} * scale[ot]; a=10 b=75 c=85 d=100
    float s = fmaf(0.1f, (float)o, 0.8f);  // {0.8,0.9,1.0,1.1,1.2}
    float dc = aisdiff5(pd, td, 22.0f * s, 35.0f * s, 45.0f * s,
                        55.0f * s, 65.0f * s);
    float mc = wmid_f(td, pd, 10.0f, 75.0f, 85.0f, 100.0f,
                      0.1f, -0.1f, 9.5f, -6.9314718e-3f);
    L += fabsf(pd - td) * sW[(int)dc] * mc;

    // ---- neck: thr {0.2,0.5,1.0,1.5,2.0}; a=0.15 b=1.5 c=1.7 d=1.9
    float dn = aisdiff5(pn, tn, 0.2f, 0.5f, 1.0f, 1.5f, 2.0f);
    float mn = wmid_f(tn, pn, 0.15f, 1.5f, 1.7f, 1.9f,
                      6.6666667f, -5.0f, 9.5f, -0.36481431f);
    L += fabsf(pn - tn) * sW[(int)dn] * mn;

    return L;
}

__global__ void __launch_bounds__(256)
loss_kernel(const float* __restrict__ pred,
            const float* __restrict__ tru,
            const int* __restrict__ ot,
            int ngroups, int nrows) {
    __shared__ float sW[8];
    if (threadIdx.x == 0) {
        sW[0] = 1.0f;    sW[1] = 1.1f;     sW[2] = 1.21f;
        sW[3] = 1.331f;  sW[4] = 1.4641f;  sW[5] = 1.61051f;
    }
    __syncthreads();

    const float4* __restrict__ pv = (const float4*)pred;
    const float4* __restrict__ tv = (const float4*)tru;
    const int4* __restrict__ ov = (const int4*)ot;

    int tid = blockIdx.x * blockDim.x + threadIdx.x;
    int stride = gridDim.x * blockDim.x;

    float acc = 0.0f;
    for (int g = tid; g < ngroups; g += stride) {
        float4 p0 = pv[3 * g + 0];
        float4 p1 = pv[3 * g + 1];
        float4 p2 = pv[3 * g + 2];
        float4 t0 = tv[3 * g + 0];
        float4 t1 = tv[3 * g + 1];
        float4 t2 = tv[3 * g + 2];
        int4 o = ov[g];
        acc += row_loss(sW, p0.x, p0.y, p0.z, t0.x, t0.y, t0.z, o.x);
        acc += row_loss(sW, p0.w, p1.x, p1.y, t0.w, t1.x, t1.y, o.y);
        acc += row_loss(sW, p1.z, p1.w, p2.x, t1.z, t1.w, t2.x, o.z);
        acc += row_loss(sW, p2.y, p2.z, p2.w, t2.y, t2.z, t2.w, o.w);
    }

    // tail rows (B not divisible by 4 — not hit for B=4194304, kept for safety)
    for (int r = 4 * ngroups + tid; r < nrows; r += stride) {
        acc += row_loss(sW, pred[3 * r + 0], pred[3 * r + 1], pred[3 * r + 2],
                        tru[3 * r + 0], tru[3 * r + 1], tru[3 * r + 2], ot[r]);
    }

    // warp reduce
    #pragma unroll
    for (int off = 16; off > 0; off >>= 1)
        acc += __shfl_xor_sync(0xffffffffu, acc, off);

    __shared__ float warpsum[8];
    int lane = threadIdx.x & 31;
    int warp = threadIdx.x >> 5;
    if (lane == 0) warpsum[warp] = acc;
    __syncthreads();

    if (warp == 0) {
        float v = (lane < (blockDim.x >> 5)) ? warpsum[lane] : 0.0f;
        #pragma unroll
        for (int off = 4; off > 0; off >>= 1)
            v += __shfl_xor_sync(0xffffffffu, v, off);
        if (lane == 0) atomicAdd(&g_sum, (double)v);
    }
}

__global__ void finalize_kernel(float* out, double invN) {
    out[0] = (float)(g_sum * invN);
}

extern "C" void kernel_launch(void* const* d_in, const int* in_sizes, int n_in,
                              void* d_out, int out_size) {
    const float* pred = (const float*)d_in[0];
    const float* tru  = (const float*)d_in[1];
    const int*   ot   = (const int*)d_in[2];
    float* out = (float*)d_out;

    int B = in_sizes[0] / 3;
    int ngroups = B / 4;

    zero_kernel<<<1, 1>>>();

    int threads = 256;
    int blocks = (ngroups + threads - 1) / threads;
    if (blocks < 1) blocks = 1;
    if (blocks > 16384) blocks = 16384;
    loss_kernel<<<blocks, threads>>>(pred, tru, ot, ngroups, B);

    finalize_kernel<<<1, 1>>>(out, 1.0 / (double)B);
}